// round 3
// baseline (speedup 1.0000x reference)
#include <cuda_runtime.h>
#include <cuda_fp16.h>

#define BB 256   // batch
#define SS 256   // seq len / steps
#define EE 2     // encoder dim
#define DD 128   // decoder dim
#define GG 512   // 4*D gates

// Packed fp16 LSTM hidden weights (see prep_kernel). 128 KB -> L1-resident.
__device__ __align__(16) __half2 g_Wpack[32 * 256 * 4];
__device__ float g_w1sum[SS];
__device__ float g_bias[GG];

__device__ __forceinline__ float tanh_fast(float x) {
    float y;
    asm("tanh.approx.f32 %0, %1;" : "=f"(y) : "f"(x));
    return y;
}
__device__ __forceinline__ float sigmoid_fast(float x) {
    return fmaf(tanh_fast(0.5f * x), 0.5f, 0.5f);
}
__device__ __forceinline__ unsigned long long pack2(float a, float b) {
    unsigned long long r;
    asm("mov.b64 %0, {%1,%2};" : "=l"(r) : "f"(a), "f"(b));
    return r;
}

// ---------------------------------------------------------------------------
// Prep kernel: pack W_hh to fp16 pairs, row-sum W1_w, fuse biases. One-time.
// ---------------------------------------------------------------------------
__global__ void prep_kernel(const float* __restrict__ W1_w,
                            const float* __restrict__ W_hh,
                            const float* __restrict__ b_ih,
                            const float* __restrict__ b_hh) {
    int blk = blockIdx.x;
    int t = threadIdx.x;
    if (blk < 128) {
        int idx = blk * 256 + t;          // 0..32767
        int c = idx >> 10;                // d-chunk 0..31
        int u = (idx >> 2) & 255;         // gate pair owner
        int k = idx & 3;
        int d = 4 * c + k;
        float lo = W_hh[(2 * u) * DD + d];
        float hi = W_hh[(2 * u + 1) * DD + d];
        g_Wpack[idx] = __halves2half2(__float2half_rn(lo), __float2half_rn(hi));
    } else {
        int lane = t & 31, w = t >> 5;
        for (int r = 0; r < 32; r++) {
            int s = w * 32 + r;
            float acc = 0.f;
            #pragma unroll
            for (int i = 0; i < 8; i++) acc += W1_w[s * SS + lane + 32 * i];
            #pragma unroll
            for (int off = 16; off; off >>= 1)
                acc += __shfl_xor_sync(0xffffffffu, acc, off);
            if (lane == 0) g_w1sum[s] = acc;
        }
        g_bias[t]       = b_ih[t]       + b_hh[t];
        g_bias[t + 256] = b_ih[t + 256] + b_hh[t + 256];
    }
}

// ---------------------------------------------------------------------------
// Main kernel: one CTA per batch element, 256 threads, 256 LSTM steps.
// ---------------------------------------------------------------------------
__global__ __launch_bounds__(256, 2)
void decoder_kernel(const float* __restrict__ enc,   // [B,S,E]
                    const float* __restrict__ W1_b,  // [S]
                    const float* __restrict__ W2_w,  // [S,2S]
                    const float* __restrict__ W2_b,  // [S]
                    const float* __restrict__ W_ih,  // [4D,E]
                    float* __restrict__ out)         // [S,B,D]
{
    // Pair-packed attention tables: pair p covers s = 2p, 2p+1
    __shared__ __align__(16) float4 sAC[128];      // {a0,a1, c0,c1}
    __shared__ __align__(16) float4 sE[128];       // {e0(2p),e0(2p+1), e1(2p),e1(2p+1)}
    __shared__ __align__(16) float  ebuf[2 * SS];
    __shared__ float a_st[SS];
    __shared__ __align__(16) float4 red[DD];       // half-1 partials {Z,n0,n1,_}
    __shared__ float gates_s[GG];
    __shared__ __align__(16) float h_s[DD];
    __shared__ float c_s[DD];
    __shared__ __align__(16) float2 wred[4];

    const int b = blockIdx.x;
    const int t = threadIdx.x;
    const int lane = t & 31;
    const int warp = t >> 5;

    // ---- per-b init ----
    ebuf[t]       = enc[b * (2 * SS) + t];
    ebuf[t + 256] = enc[b * (2 * SS) + t + 256];
    if (t < DD) { h_s[t] = 0.f; c_s[t] = 0.f; }
    __syncthreads();

    // a[s] = encflat . W2_w[s,:] + W2_b[s] + W1_b[s]
    {
        const float4* W2w4 = (const float4*)W2_w;
        const float4* e4   = (const float4*)ebuf;
        for (int r = 0; r < 32; r++) {
            int s = warp * 32 + r;
            float acc = 0.f;
            #pragma unroll
            for (int i = 0; i < 4; i++) {
                float4 wv = W2w4[s * 128 + lane + 32 * i];
                float4 ev = e4[lane + 32 * i];
                acc += wv.x * ev.x + wv.y * ev.y + wv.z * ev.z + wv.w * ev.w;
            }
            #pragma unroll
            for (int off = 16; off; off >>= 1)
                acc += __shfl_xor_sync(0xffffffffu, acc, off);
            if (lane == 0) a_st[s] = acc + W2_b[s] + W1_b[s];
        }
    }
    __syncthreads();
    if (t < 128) {
        int p = t;
        sAC[p] = make_float4(a_st[2 * p], a_st[2 * p + 1],
                             g_w1sum[2 * p], g_w1sum[2 * p + 1]);
        sE[p]  = make_float4(ebuf[4 * p], ebuf[4 * p + 2],
                             ebuf[4 * p + 1], ebuf[4 * p + 3]);
    }
    __syncthreads();

    // packed Horner constants for exp(t), t in [-1,1], degree 7 Taylor
    const unsigned long long C7  = pack2(1.9841270e-4f, 1.9841270e-4f);
    const unsigned long long C6  = pack2(1.3888889e-3f, 1.3888889e-3f);
    const unsigned long long C5  = pack2(8.3333333e-3f, 8.3333333e-3f);
    const unsigned long long C4  = pack2(4.1666668e-2f, 4.1666668e-2f);
    const unsigned long long C3  = pack2(0.16666667f,   0.16666667f);
    const unsigned long long C2  = pack2(0.5f, 0.5f);
    const unsigned long long ONE = pack2(1.0f, 1.0f);

    // thread roles
    const int d    = t & 127;   // attention dim
    const int half = t >> 7;    // attention s-half (warp-uniform)
    const float biasA = g_bias[2 * t];
    const float biasB = g_bias[2 * t + 1];
    const float wA0 = W_ih[4 * t + 0], wA1 = W_ih[4 * t + 1];
    const float wB0 = W_ih[4 * t + 2], wB1 = W_ih[4 * t + 3];
    const __half2* wp = g_Wpack + t * 4;
    const double2* pAC = (const double2*)(sAC + half * 64);
    const double2* pE  = (const double2*)(sE  + half * 64);

    for (int step = 0; step < SS; step++) {
        // ---- Phase A: attention. 2 s-elements/iter, exp via packed poly ----
        const float hd = h_s[d];
        unsigned long long hd2;
        asm("mov.b64 %0, {%1,%1};" : "=l"(hd2) : "f"(hd));
        unsigned long long Z2 = 0ull, n02 = 0ull, n12 = 0ull; // {0.f,0.f}

        #pragma unroll 8
        for (int i = 0; i < 64; i++) {
            double2 acd = pAC[i];               // LDS.128 broadcast
            double2 eed = pE[i];                // LDS.128 broadcast
            unsigned long long ap  = __double_as_longlong(acd.x);
            unsigned long long cp  = __double_as_longlong(acd.y);
            unsigned long long e0p = __double_as_longlong(eed.x);
            unsigned long long e1p = __double_as_longlong(eed.y);
            unsigned long long x2;
            asm("fma.rn.f32x2 %0, %1, %2, %3;" : "=l"(x2) : "l"(hd2), "l"(cp), "l"(ap));
            float x0, x1;
            asm("mov.b64 {%0,%1}, %2;" : "=f"(x0), "=f"(x1) : "l"(x2));
            float t0 = tanh_fast(x0);           // 1 MUFU per s
            float t1 = tanh_fast(x1);
            unsigned long long t2;
            asm("mov.b64 %0, {%1,%2};" : "=l"(t2) : "f"(t0), "f"(t1));
            unsigned long long p;                // exp(t) via Horner, fma pipe
            asm("fma.rn.f32x2 %0, %1, %2, %3;" : "=l"(p) : "l"(C7), "l"(t2), "l"(C6));
            asm("fma.rn.f32x2 %0, %0, %1, %2;" : "+l"(p) : "l"(t2), "l"(C5));
            asm("fma.rn.f32x2 %0, %0, %1, %2;" : "+l"(p) : "l"(t2), "l"(C4));
            asm("fma.rn.f32x2 %0, %0, %1, %2;" : "+l"(p) : "l"(t2), "l"(C3));
            asm("fma.rn.f32x2 %0, %0, %1, %2;" : "+l"(p) : "l"(t2), "l"(C2));
            asm("fma.rn.f32x2 %0, %0, %1, %2;" : "+l"(p) : "l"(t2), "l"(ONE));
            asm("fma.rn.f32x2 %0, %0, %1, %2;" : "+l"(p) : "l"(t2), "l"(ONE));
            asm("add.rn.f32x2 %0, %0, %1;"     : "+l"(Z2) : "l"(p));
            asm("fma.rn.f32x2 %0, %1, %2, %0;" : "+l"(n02) : "l"(p), "l"(e0p));
            asm("fma.rn.f32x2 %0, %1, %2, %0;" : "+l"(n12) : "l"(p), "l"(e1p));
        }
        float Zl, Zh, a0, a1, b0, b1;
        asm("mov.b64 {%0,%1}, %2;" : "=f"(Zl), "=f"(Zh) : "l"(Z2));
        asm("mov.b64 {%0,%1}, %2;" : "=f"(a0), "=f"(a1) : "l"(n02));
        asm("mov.b64 {%0,%1}, %2;" : "=f"(b0), "=f"(b1) : "l"(n12));
        float Z = Zl + Zh, n0 = a0 + a1, n1 = b0 + b1;

        if (half) red[d] = make_float4(Z, n0, n1, 0.f);
        __syncthreads();                             // B1

        if (half == 0) {
            float4 r = red[d];
            Z += r.x; n0 += r.y; n1 += r.z;
            float inv = __fdividef(1.f, Z);
            float cx0 = n0 * inv, cx1 = n1 * inv;
            #pragma unroll
            for (int off = 16; off; off >>= 1) {
                cx0 += __shfl_xor_sync(0xffffffffu, cx0, off);
                cx1 += __shfl_xor_sync(0xffffffffu, cx1, off);
            }
            if (lane == 0) wred[warp] = make_float2(cx0, cx1);
        }
        __syncthreads();                             // B2

        float2 r0 = wred[0], r1 = wred[1], r2 = wred[2], r3 = wred[3];
        const float x0c = (r0.x + r1.x + r2.x + r3.x) * (1.f / 128.f);
        const float x1c = (r0.y + r1.y + r2.y + r3.y) * (1.f / 128.f);

        // ---- Phase B: LSTM gates (fp16 weights, L1-resident) ----
        float accA = fmaf(x0c, wA0, fmaf(x1c, wA1, biasA));
        float accB = fmaf(x0c, wB0, fmaf(x1c, wB1, biasB));
        {
            const float4* h4 = (const float4*)h_s;
            #pragma unroll 8
            for (int c = 0; c < 32; c++) {
                float4 hv = h4[c];                              // broadcast
                uint4 wr = *(const uint4*)(wp + c * 1024);      // LDG.128, L1 hit
                float2 f0 = __half22float2(*(const __half2*)&wr.x);
                float2 f1 = __half22float2(*(const __half2*)&wr.y);
                float2 f2 = __half22float2(*(const __half2*)&wr.z);
                float2 f3 = __half22float2(*(const __half2*)&wr.w);
                accA = fmaf(hv.x, f0.x, accA); accB = fmaf(hv.x, f0.y, accB);
                accA = fmaf(hv.y, f1.x, accA); accB = fmaf(hv.y, f1.y, accB);
                accA = fmaf(hv.z, f2.x, accA); accB = fmaf(hv.z, f2.y, accB);
                accA = fmaf(hv.w, f3.x, accA); accB = fmaf(hv.w, f3.y, accB);
            }
        }
        gates_s[2 * t]     = accA;
        gates_s[2 * t + 1] = accB;
        __syncthreads();                             // B3

        // ---- c/h update + output ----
        if (t < DD) {
            float gi = gates_s[t];
            float gf = gates_s[t + 128];
            float gg = gates_s[t + 256];
            float go = gates_s[t + 384];
            float si = sigmoid_fast(gi);
            float sf = sigmoid_fast(gf);
            float so = sigmoid_fast(go);
            float c = fmaf(sf, c_s[t], si * tanh_fast(gg));
            float h = so * tanh_fast(c);
            c_s[t] = c;
            h_s[t] = h;
            out[(size_t)step * (BB * DD) + b * DD + t] = h;
        }
        __syncthreads();                             // B4
    }
}

// ---------------------------------------------------------------------------
extern "C" void kernel_launch(void* const* d_in, const int* in_sizes, int n_in,
                              void* d_out, int out_size) {
    const float* enc  = (const float*)d_in[0];
    const float* W1_w = (const float*)d_in[1];
    const float* W1_b = (const float*)d_in[2];
    const float* W2_w = (const float*)d_in[3];
    const float* W2_b = (const float*)d_in[4];
    const float* W_ih = (const float*)d_in[5];
    const float* W_hh = (const float*)d_in[6];
    const float* b_ih = (const float*)d_in[7];
    const float* b_hh = (const float*)d_in[8];
    float* out = (float*)d_out;

    prep_kernel<<<129, 256>>>(W1_w, W_hh, b_ih, b_hh);
    decoder_kernel<<<BB, 256>>>(enc, W1_b, W2_w, W2_b, W_ih, out);
}

// round 4
// speedup vs baseline: 1.0962x; 1.0962x over previous
#include <cuda_runtime.h>
#include <cuda_fp16.h>

#define BB 256   // batch
#define SS 256   // seq len / steps
#define DD 128   // decoder dim
#define GG 512   // 4*D gates

// bf16x2-packed LSTM hidden weights: word idx = c*1024 + u*4 + k, where
// c = d/4 chunk, u = gate-pair owner thread, k = d%4.
// word = bf16x2{ W_hh[2u][d] (lo), W_hh[2u+1][d] (hi) }. 64 KB -> L1-resident.
__device__ __align__(16) unsigned int g_Wpack[32 * 256 * 4];
__device__ float g_w1sum[SS];
__device__ float g_bias[GG];

__device__ __forceinline__ float tanh_fast(float x) {
    float y;
    asm("tanh.approx.f32 %0, %1;" : "=f"(y) : "f"(x));
    return y;
}
__device__ __forceinline__ float sigmoid_fast(float x) {
    return fmaf(tanh_fast(0.5f * x), 0.5f, 0.5f);
}
__device__ __forceinline__ unsigned long long pack2(float a, float b) {
    unsigned long long r;
    asm("mov.b64 %0, {%1,%2};" : "=l"(r) : "f"(a), "f"(b));
    return r;
}
// bf16 lo/hi of a bf16x2 word -> f32 (PRMT on alu pipe)
__device__ __forceinline__ float bf_lo(unsigned int v) {
    return __uint_as_float(__byte_perm(v, 0u, 0x1044));
}
__device__ __forceinline__ float bf_hi(unsigned int v) {
    return __uint_as_float(__byte_perm(v, 0u, 0x3244));
}

// ---------------------------------------------------------------------------
// Prep kernel: pack W_hh to bf16x2, row-sum W1_w, fuse biases. One-time.
// ---------------------------------------------------------------------------
__global__ void prep_kernel(const float* __restrict__ W1_w,
                            const float* __restrict__ W_hh,
                            const float* __restrict__ b_ih,
                            const float* __restrict__ b_hh) {
    int blk = blockIdx.x;
    int t = threadIdx.x;
    if (blk < 128) {
        int idx = blk * 256 + t;          // 0..32767
        int c = idx >> 10;                // d-chunk 0..31
        int u = (idx >> 2) & 255;         // gate-pair owner thread
        int k = idx & 3;
        int d = 4 * c + k;
        float lo = W_hh[(2 * u) * DD + d];
        float hi = W_hh[(2 * u + 1) * DD + d];
        unsigned int r;
        asm("cvt.rn.bf16x2.f32 %0, %1, %2;" : "=r"(r) : "f"(hi), "f"(lo));
        g_Wpack[idx] = r;
    } else {
        int lane = t & 31, w = t >> 5;
        for (int r = 0; r < 32; r++) {
            int s = w * 32 + r;
            float acc = 0.f;
            #pragma unroll
            for (int i = 0; i < 8; i++) acc += W1_w[s * SS + lane + 32 * i];
            #pragma unroll
            for (int off = 16; off; off >>= 1)
                acc += __shfl_xor_sync(0xffffffffu, acc, off);
            if (lane == 0) g_w1sum[s] = acc;
        }
        g_bias[t]       = b_ih[t]       + b_hh[t];
        g_bias[t + 256] = b_ih[t + 256] + b_hh[t + 256];
    }
}

// ---------------------------------------------------------------------------
// Main kernel: one CTA per batch element, 256 threads, 256 LSTM steps.
// ---------------------------------------------------------------------------
__global__ __launch_bounds__(256, 2)
void decoder_kernel(const float* __restrict__ enc,   // [B,S,E]
                    const float* __restrict__ W1_b,  // [S]
                    const float* __restrict__ W2_w,  // [S,2S]
                    const float* __restrict__ W2_b,  // [S]
                    const float* __restrict__ W_ih,  // [4D,E]
                    float* __restrict__ out)         // [S,B,D]
{
    __shared__ __align__(16) float4 sAC[128];      // pair p: {a(2p),a(2p+1),c(2p),c(2p+1)}
    __shared__ __align__(16) float4 sE[128];       // pair p: {e0(2p),e0(2p+1),e1(2p),e1(2p+1)}
    __shared__ __align__(16) float  ebuf[2 * SS];
    __shared__ float a_st[SS];
    __shared__ __align__(16) float4 red[DD];       // half-1 partials {Z,n0,n1,_}
    __shared__ float gates_s[GG];
    __shared__ __align__(16) float h_s[DD];
    __shared__ float c_s[DD];
    __shared__ __align__(16) float2 wred[4];

    const int b = blockIdx.x;
    const int t = threadIdx.x;
    const int lane = t & 31;
    const int warp = t >> 5;

    // ---- per-b init ----
    ebuf[t]       = enc[b * (2 * SS) + t];
    ebuf[t + 256] = enc[b * (2 * SS) + t + 256];
    if (t < DD) { h_s[t] = 0.f; c_s[t] = 0.f; }
    __syncthreads();

    // a[s] = encflat . W2_w[s,:] + W2_b[s] + W1_b[s]
    {
        const float4* W2w4 = (const float4*)W2_w;
        const float4* e4   = (const float4*)ebuf;
        for (int r = 0; r < 32; r++) {
            int s = warp * 32 + r;
            float acc = 0.f;
            #pragma unroll
            for (int i = 0; i < 4; i++) {
                float4 wv = W2w4[s * 128 + lane + 32 * i];
                float4 ev = e4[lane + 32 * i];
                acc += wv.x * ev.x + wv.y * ev.y + wv.z * ev.z + wv.w * ev.w;
            }
            #pragma unroll
            for (int off = 16; off; off >>= 1)
                acc += __shfl_xor_sync(0xffffffffu, acc, off);
            if (lane == 0) a_st[s] = acc + W2_b[s] + W1_b[s];
        }
    }
    __syncthreads();
    if (t < 128) {
        int p = t;
        sAC[p] = make_float4(a_st[2 * p], a_st[2 * p + 1],
                             g_w1sum[2 * p], g_w1sum[2 * p + 1]);
        sE[p]  = make_float4(ebuf[4 * p], ebuf[4 * p + 2],
                             ebuf[4 * p + 1], ebuf[4 * p + 3]);
    }
    __syncthreads();

    // Degree-5 Chebyshev-economized poly for exp(t), t in [-1,1], abs err <= 5e-5
    const unsigned long long P5 = pack2(0.00868688f, 0.00868688f);
    const unsigned long long P4 = pack2(0.04379392f, 0.04379392f);
    const unsigned long long P3 = pack2(0.16648880f, 0.16648880f);
    const unsigned long long P2 = pack2(0.49919676f, 0.49919676f);
    const unsigned long long P1 = pack2(1.00002231f, 1.00002231f);
    const unsigned long long P0 = pack2(1.00004478f, 1.00004478f);

    // thread roles
    const int d    = t & 127;   // attention dim
    const int half = t >> 7;    // attention s-half (warp-uniform)
    const float biasA = g_bias[2 * t];
    const float biasB = g_bias[2 * t + 1];
    const float wA0 = W_ih[4 * t + 0], wA1 = W_ih[4 * t + 1];
    const float wB0 = W_ih[4 * t + 2], wB1 = W_ih[4 * t + 3];
    const uint4* wp4 = ((const uint4*)g_Wpack) + t;   // stride 256 per chunk
    const double2* pAC = (const double2*)(sAC + half * 64);
    const double2* pE  = (const double2*)(sE  + half * 64);

    for (int step = 0; step < SS; step++) {
        // ---- LSTM h-dot FIRST (independent of ctx; LDG latency hides under
        //      the attention stretch below). bf16 weights, PRMT on alu pipe. ----
        float accA = biasA, accB = biasB;
        {
            const float4* h4 = (const float4*)h_s;
            #pragma unroll 8
            for (int c = 0; c < 32; c++) {
                float4 hv = h4[c];                 // broadcast LDS.128
                uint4 wr = wp4[c * 256];           // LDG.128, L1-resident
                accA = fmaf(hv.x, bf_lo(wr.x), accA);
                accB = fmaf(hv.x, bf_hi(wr.x), accB);
                accA = fmaf(hv.y, bf_lo(wr.y), accA);
                accB = fmaf(hv.y, bf_hi(wr.y), accB);
                accA = fmaf(hv.z, bf_lo(wr.z), accA);
                accB = fmaf(hv.z, bf_hi(wr.z), accB);
                accA = fmaf(hv.w, bf_lo(wr.w), accA);
                accB = fmaf(hv.w, bf_hi(wr.w), accB);
            }
        }

        // ---- Attention: 2 s-elements/iter, exp via deg-5 packed Horner ----
        const float hd = h_s[d];
        unsigned long long hd2;
        asm("mov.b64 %0, {%1,%1};" : "=l"(hd2) : "f"(hd));
        unsigned long long Z2 = 0ull, n02 = 0ull, n12 = 0ull;

        #pragma unroll 8
        for (int i = 0; i < 64; i++) {
            double2 acd = pAC[i];               // LDS.128 broadcast
            double2 eed = pE[i];                // LDS.128 broadcast
            unsigned long long ap  = __double_as_longlong(acd.x);
            unsigned long long cp  = __double_as_longlong(acd.y);
            unsigned long long e0p = __double_as_longlong(eed.x);
            unsigned long long e1p = __double_as_longlong(eed.y);
            unsigned long long x2;
            asm("fma.rn.f32x2 %0, %1, %2, %3;" : "=l"(x2) : "l"(hd2), "l"(cp), "l"(ap));
            float x0, x1;
            asm("mov.b64 {%0,%1}, %2;" : "=f"(x0), "=f"(x1) : "l"(x2));
            float t0 = tanh_fast(x0);           // 1 MUFU per s
            float t1 = tanh_fast(x1);
            unsigned long long t2;
            asm("mov.b64 %0, {%1,%2};" : "=l"(t2) : "f"(t0), "f"(t1));
            unsigned long long p;                // exp(t), fma pipe, 5 FFMA2
            asm("fma.rn.f32x2 %0, %1, %2, %3;" : "=l"(p) : "l"(P5), "l"(t2), "l"(P4));
            asm("fma.rn.f32x2 %0, %0, %1, %2;" : "+l"(p) : "l"(t2), "l"(P3));
            asm("fma.rn.f32x2 %0, %0, %1, %2;" : "+l"(p) : "l"(t2), "l"(P2));
            asm("fma.rn.f32x2 %0, %0, %1, %2;" : "+l"(p) : "l"(t2), "l"(P1));
            asm("fma.rn.f32x2 %0, %0, %1, %2;" : "+l"(p) : "l"(t2), "l"(P0));
            asm("add.rn.f32x2 %0, %0, %1;"     : "+l"(Z2) : "l"(p));
            asm("fma.rn.f32x2 %0, %1, %2, %0;" : "+l"(n02) : "l"(p), "l"(e0p));
            asm("fma.rn.f32x2 %0, %1, %2, %0;" : "+l"(n12) : "l"(p), "l"(e1p));
        }
        float Zl, Zh, a0, a1, b0, b1;
        asm("mov.b64 {%0,%1}, %2;" : "=f"(Zl), "=f"(Zh) : "l"(Z2));
        asm("mov.b64 {%0,%1}, %2;" : "=f"(a0), "=f"(a1) : "l"(n02));
        asm("mov.b64 {%0,%1}, %2;" : "=f"(b0), "=f"(b1) : "l"(n12));
        float Z = Zl + Zh, n0 = a0 + a1, n1 = b0 + b1;

        if (half) red[d] = make_float4(Z, n0, n1, 0.f);
        __syncthreads();                             // B1

        if (half == 0) {
            float4 r = red[d];
            Z += r.x; n0 += r.y; n1 += r.z;
            float inv = __fdividef(1.f, Z);
            float cx0 = n0 * inv, cx1 = n1 * inv;
            #pragma unroll
            for (int off = 16; off; off >>= 1) {
                cx0 += __shfl_xor_sync(0xffffffffu, cx0, off);
                cx1 += __shfl_xor_sync(0xffffffffu, cx1, off);
            }
            if (lane == 0) wred[warp] = make_float2(cx0, cx1);
        }
        __syncthreads();                             // B2

        float2 r0 = wred[0], r1 = wred[1], r2 = wred[2], r3 = wred[3];
        const float x0c = (r0.x + r1.x + r2.x + r3.x) * (1.f / 128.f);
        const float x1c = (r0.y + r1.y + r2.y + r3.y) * (1.f / 128.f);

        // fold ctx into gates
        accA = fmaf(x0c, wA0, fmaf(x1c, wA1, accA));
        accB = fmaf(x0c, wB0, fmaf(x1c, wB1, accB));
        gates_s[2 * t]     = accA;
        gates_s[2 * t + 1] = accB;
        __syncthreads();                             // B3

        // ---- c/h update + output ----
        if (t < DD) {
            float gi = gates_s[t];
            float gf = gates_s[t + 128];
            float gg = gates_s[t + 256];
            float go = gates_s[t + 384];
            float si = sigmoid_fast(gi);
            float sf = sigmoid_fast(gf);
            float so = sigmoid_fast(go);
            float c = fmaf(sf, c_s[t], si * tanh_fast(gg));
            float h = so * tanh_fast(c);
            c_s[t] = c;
            h_s[t] = h;
            out[(size_t)step * (BB * DD) + b * DD + t] = h;
        }
        __syncthreads();                             // B4
    }
}

// ---------------------------------------------------------------------------
extern "C" void kernel_launch(void* const* d_in, const int* in_sizes, int n_in,
                              void* d_out, int out_size) {
    const float* enc  = (const float*)d_in[0];
    const float* W1_w = (const float*)d_in[1];
    const float* W1_b = (const float*)d_in[2];
    const float* W2_w = (const float*)d_in[3];
    const float* W2_b = (const float*)d_in[4];
    const float* W_ih = (const float*)d_in[5];
    const float* W_hh = (const float*)d_in[6];
    const float* b_ih = (const float*)d_in[7];
    const float* b_hh = (const float*)d_in[8];
    float* out = (float*)d_out;

    prep_kernel<<<129, 256>>>(W1_w, W_hh, b_ih, b_hh);
    decoder_kernel<<<BB, 256>>>(enc, W1_b, W2_w, W2_b, W_ih, out);
}